// round 1
// baseline (speedup 1.0000x reference)
#include <cuda_runtime.h>
#include <math.h>

#define B  32
#define D  512
#define M  10000
#define KTOP 5
#define R3 32768           // 32*32*32
#define KPB 64             // keys per block in sim kernel
#define EPS 1e-12f

// -------- device scratch (no allocation allowed) --------
__device__ float g_rq[B];            // 1/max(||x_b||, eps)
__device__ float g_sim[B * M];       // similarity matrix [b][m]
__device__ int   g_topidx[B * KTOP];
__device__ float g_topval[B * KTOP];

// ============================================================
// Kernel 1: per-row reciprocal norms of x
// ============================================================
__global__ void k_qnorm(const float* __restrict__ x) {
    int b = blockIdx.x;            // 32 blocks
    int t = threadIdx.x;           // 128 threads
    float s = 0.f;
    #pragma unroll
    for (int d = t; d < D; d += 128) {
        float v = x[b * D + d];
        s += v * v;
    }
    #pragma unroll
    for (int o = 16; o > 0; o >>= 1) s += __shfl_down_sync(0xFFFFFFFFu, s, o);
    __shared__ float ws[4];
    if ((t & 31) == 0) ws[t >> 5] = s;
    __syncthreads();
    if (t == 0) {
        float tot = ws[0] + ws[1] + ws[2] + ws[3];
        g_rq[b] = 1.0f / fmaxf(sqrtf(tot), EPS);
    }
}

// ============================================================
// Kernel 2: sim[b][m] = dot(x_b, k_m) * rq[b] * rk[m]
// Block: 256 threads -> 32 b x 64 keys tile. Per thread: 8 b x 1 key.
// Keys staged in smem (d4-transposed float4), x via broadcast LDG.
// ============================================================
__global__ void __launch_bounds__(256, 4) k_sim(const float* __restrict__ x,
                                                const float* __restrict__ keys) {
    __shared__ float4 ksh[8][KPB + 1];   // [d4-in-tile][key], padded
    __shared__ float  s_rk[KPB];

    const int tid  = threadIdx.x;
    const int kcol = tid & 63;           // key column 0..63
    const int brow = tid >> 6;           // 0..3 -> b in [brow*8, brow*8+8)
    const int lane = tid & 31;
    const int w    = tid >> 5;
    const int m0   = blockIdx.x * KPB;
    const int mg   = m0 + kcol;

    const float4* __restrict__ x4    = (const float4*)x;     // row stride 128
    const float4* __restrict__ keys4 = (const float4*)keys;  // row stride 128

    float acc[8];
    #pragma unroll
    for (int i = 0; i < 8; ++i) acc[i] = 0.f;
    float knorm2 = 0.f;

    // 16 tiles of DK=32 (8 float4) along D
    for (int t = 0; t < D / 32; ++t) {
        // cooperative tile load: warp w loads 4 keys per pass, 128B contiguous per key
        #pragma unroll
        for (int p = 0; p < 2; ++p) {
            int kl  = p * 32 + w * 4 + (lane >> 3);  // key local 0..63
            int d4  = lane & 7;                      // float4 index within tile
            int mgl = m0 + kl;
            float4 v = make_float4(0.f, 0.f, 0.f, 0.f);
            if (mgl < M) v = keys4[(size_t)mgl * 128 + t * 8 + d4];
            ksh[d4][kl] = v;
        }
        __syncthreads();

        #pragma unroll
        for (int d4 = 0; d4 < 8; ++d4) {
            float4 kv = ksh[d4][kcol];
            if (brow == 0)
                knorm2 = fmaf(kv.x, kv.x, fmaf(kv.y, kv.y,
                          fmaf(kv.z, kv.z, fmaf(kv.w, kv.w, knorm2))));
            #pragma unroll
            for (int i = 0; i < 8; ++i) {
                float4 q = x4[(brow * 8 + i) * 128 + t * 8 + d4];  // broadcast
                acc[i] = fmaf(q.x, kv.x, acc[i]);
                acc[i] = fmaf(q.y, kv.y, acc[i]);
                acc[i] = fmaf(q.z, kv.z, acc[i]);
                acc[i] = fmaf(q.w, kv.w, acc[i]);
            }
        }
        __syncthreads();
    }

    if (brow == 0) s_rk[kcol] = 1.0f / fmaxf(sqrtf(knorm2), EPS);
    __syncthreads();

    if (mg < M) {
        float rk = s_rk[kcol];
        #pragma unroll
        for (int i = 0; i < 8; ++i) {
            int b = brow * 8 + i;
            g_sim[b * M + mg] = acc[i] * g_rq[b] * rk;
        }
    }
}

// ============================================================
// Kernel 3: top-5 per batch row. One block per b, sim row in smem.
// Tie-break: lowest index (matches jax.lax.top_k).
// ============================================================
__global__ void __launch_bounds__(256) k_topk() {
    __shared__ float s_sim[M];       // 40000 B
    __shared__ float s_val[256];
    __shared__ int   s_idx[256];

    const int b   = blockIdx.x;
    const int tid = threadIdx.x;

    for (int m = tid; m < M; m += 256) s_sim[m] = g_sim[b * M + m];
    __syncthreads();

    for (int k = 0; k < KTOP; ++k) {
        float best = -INFINITY;
        int   bi   = M;
        for (int m = tid; m < M; m += 256) {
            float v = s_sim[m];
            if (v > best) { best = v; bi = m; }   // increasing m keeps lowest idx on ties
        }
        s_val[tid] = best;
        s_idx[tid] = bi;
        __syncthreads();
        #pragma unroll
        for (int s = 128; s > 0; s >>= 1) {
            if (tid < s) {
                float v2 = s_val[tid + s];
                int   i2 = s_idx[tid + s];
                if (v2 > s_val[tid] || (v2 == s_val[tid] && i2 < s_idx[tid])) {
                    s_val[tid] = v2;
                    s_idx[tid] = i2;
                }
            }
            __syncthreads();
        }
        if (tid == 0) {
            g_topidx[b * KTOP + k] = s_idx[0];
            g_topval[b * KTOP + k] = s_val[0];
            s_sim[s_idx[0]] = -INFINITY;
        }
        __syncthreads();
    }
}

// ============================================================
// Kernel 4: gather voxel grids + write idx/vals tail.
// 160 pairs x 8 chunks of 16KB each (float4).
// ============================================================
__global__ void __launch_bounds__(256) k_gather(const float* __restrict__ vals,
                                                float* __restrict__ out,
                                                int out_size) {
    const int pair  = blockIdx.x >> 3;   // 0..159
    const int chunk = blockIdx.x & 7;    // 0..7
    const int t     = threadIdx.x;

    const int idx = g_topidx[pair];
    const float4* __restrict__ src =
        (const float4*)(vals + (size_t)idx * R3) + chunk * 1024;
    float4* __restrict__ dst =
        (float4*)(out + (size_t)pair * R3) + chunk * 1024;

    #pragma unroll
    for (int i = 0; i < 4; ++i) dst[t + i * 256] = src[t + i * 256];

    if (blockIdx.x == 0) {
        const int total = B * KTOP * R3;   // 5242880
        if (out_size >= total + 2 * B * KTOP && t < B * KTOP) {
            out[total + t]            = (float)g_topidx[t];
            out[total + B * KTOP + t] = g_topval[t];
        }
    }
}

// ============================================================
extern "C" void kernel_launch(void* const* d_in, const int* in_sizes, int n_in,
                              void* d_out, int out_size) {
    const float* x    = (const float*)d_in[0];  // (32, 512)
    const float* keys = (const float*)d_in[1];  // (10000, 512)
    const float* vals = (const float*)d_in[2];  // (10000, 32, 32, 32)
    // d_in[3] = top_k (int scalar) -- fixed at 5 per problem shape

    float* out = (float*)d_out;

    k_qnorm<<<B, 128>>>(x);
    k_sim<<<(M + KPB - 1) / KPB, 256>>>(x, keys);   // 157 blocks
    k_topk<<<B, 256>>>();
    k_gather<<<B * KTOP * 8, 256>>>(vals, out, out_size);
}

// round 2
// speedup vs baseline: 1.0005x; 1.0005x over previous
#include <cuda_runtime.h>
#include <math.h>

#define B  32
#define D  512
#define M  10000
#define KTOP 5
#define R3 32768           // 32*32*32
#define KPB 64             // keys per block in sim kernel
#define EPS 1e-12f

// -------- device scratch (no allocation allowed) --------
__device__ float g_rq[B];            // 1/max(||x_b||, eps)
__device__ float g_sim[B * M];       // similarity matrix [b][m]
__device__ int   g_topidx[B * KTOP];
__device__ float g_topval[B * KTOP];

// ============================================================
// Kernel 1: per-row reciprocal norms of x
// ============================================================
__global__ void k_qnorm(const float* __restrict__ x) {
    int b = blockIdx.x;            // 32 blocks
    int t = threadIdx.x;           // 128 threads
    float s = 0.f;
    #pragma unroll
    for (int d = t; d < D; d += 128) {
        float v = x[b * D + d];
        s += v * v;
    }
    #pragma unroll
    for (int o = 16; o > 0; o >>= 1) s += __shfl_down_sync(0xFFFFFFFFu, s, o);
    __shared__ float ws[4];
    if ((t & 31) == 0) ws[t >> 5] = s;
    __syncthreads();
    if (t == 0) {
        float tot = ws[0] + ws[1] + ws[2] + ws[3];
        g_rq[b] = 1.0f / fmaxf(sqrtf(tot), EPS);
    }
}

// ============================================================
// Kernel 2: sim[b][m] = dot(x_b, k_m) * rq[b] * rk[m]
// Block: 256 threads -> 32 b x 64 keys tile. Per thread: 8 b x 1 key.
// Keys staged in smem (d4-transposed float4), x via broadcast LDG.
// ============================================================
__global__ void __launch_bounds__(256, 4) k_sim(const float* __restrict__ x,
                                                const float* __restrict__ keys) {
    __shared__ float4 ksh[8][KPB + 1];   // [d4-in-tile][key], padded
    __shared__ float  s_rk[KPB];

    const int tid  = threadIdx.x;
    const int kcol = tid & 63;           // key column 0..63
    const int brow = tid >> 6;           // 0..3 -> b in [brow*8, brow*8+8)
    const int lane = tid & 31;
    const int w    = tid >> 5;
    const int m0   = blockIdx.x * KPB;
    const int mg   = m0 + kcol;

    const float4* __restrict__ x4    = (const float4*)x;     // row stride 128
    const float4* __restrict__ keys4 = (const float4*)keys;  // row stride 128

    float acc[8];
    #pragma unroll
    for (int i = 0; i < 8; ++i) acc[i] = 0.f;
    float knorm2 = 0.f;

    // 16 tiles of DK=32 (8 float4) along D
    for (int t = 0; t < D / 32; ++t) {
        // cooperative tile load: warp w loads 4 keys per pass, 128B contiguous per key
        #pragma unroll
        for (int p = 0; p < 2; ++p) {
            int kl  = p * 32 + w * 4 + (lane >> 3);  // key local 0..63
            int d4  = lane & 7;                      // float4 index within tile
            int mgl = m0 + kl;
            float4 v = make_float4(0.f, 0.f, 0.f, 0.f);
            if (mgl < M) v = keys4[(size_t)mgl * 128 + t * 8 + d4];
            ksh[d4][kl] = v;
        }
        __syncthreads();

        #pragma unroll
        for (int d4 = 0; d4 < 8; ++d4) {
            float4 kv = ksh[d4][kcol];
            if (brow == 0)
                knorm2 = fmaf(kv.x, kv.x, fmaf(kv.y, kv.y,
                          fmaf(kv.z, kv.z, fmaf(kv.w, kv.w, knorm2))));
            #pragma unroll
            for (int i = 0; i < 8; ++i) {
                float4 q = x4[(brow * 8 + i) * 128 + t * 8 + d4];  // broadcast
                acc[i] = fmaf(q.x, kv.x, acc[i]);
                acc[i] = fmaf(q.y, kv.y, acc[i]);
                acc[i] = fmaf(q.z, kv.z, acc[i]);
                acc[i] = fmaf(q.w, kv.w, acc[i]);
            }
        }
        __syncthreads();
    }

    if (brow == 0) s_rk[kcol] = 1.0f / fmaxf(sqrtf(knorm2), EPS);
    __syncthreads();

    if (mg < M) {
        float rk = s_rk[kcol];
        #pragma unroll
        for (int i = 0; i < 8; ++i) {
            int b = brow * 8 + i;
            g_sim[b * M + mg] = acc[i] * g_rq[b] * rk;
        }
    }
}

// ============================================================
// Kernel 3: top-5 per batch row. One block per b, sim row in smem.
// Tie-break: lowest index (matches jax.lax.top_k).
// ============================================================
__global__ void __launch_bounds__(256) k_topk() {
    __shared__ float s_sim[M];       // 40000 B
    __shared__ float s_val[256];
    __shared__ int   s_idx[256];

    const int b   = blockIdx.x;
    const int tid = threadIdx.x;

    for (int m = tid; m < M; m += 256) s_sim[m] = g_sim[b * M + m];
    __syncthreads();

    for (int k = 0; k < KTOP; ++k) {
        float best = -INFINITY;
        int   bi   = M;
        for (int m = tid; m < M; m += 256) {
            float v = s_sim[m];
            if (v > best) { best = v; bi = m; }   // increasing m keeps lowest idx on ties
        }
        s_val[tid] = best;
        s_idx[tid] = bi;
        __syncthreads();
        #pragma unroll
        for (int s = 128; s > 0; s >>= 1) {
            if (tid < s) {
                float v2 = s_val[tid + s];
                int   i2 = s_idx[tid + s];
                if (v2 > s_val[tid] || (v2 == s_val[tid] && i2 < s_idx[tid])) {
                    s_val[tid] = v2;
                    s_idx[tid] = i2;
                }
            }
            __syncthreads();
        }
        if (tid == 0) {
            g_topidx[b * KTOP + k] = s_idx[0];
            g_topval[b * KTOP + k] = s_val[0];
            s_sim[s_idx[0]] = -INFINITY;
        }
        __syncthreads();
    }
}

// ============================================================
// Kernel 4: gather voxel grids + write idx/vals tail.
// 160 pairs x 8 chunks of 16KB each (float4).
// ============================================================
__global__ void __launch_bounds__(256) k_gather(const float* __restrict__ vals,
                                                float* __restrict__ out,
                                                int out_size) {
    const int pair  = blockIdx.x >> 3;   // 0..159
    const int chunk = blockIdx.x & 7;    // 0..7
    const int t     = threadIdx.x;

    const int idx = g_topidx[pair];
    const float4* __restrict__ src =
        (const float4*)(vals + (size_t)idx * R3) + chunk * 1024;
    float4* __restrict__ dst =
        (float4*)(out + (size_t)pair * R3) + chunk * 1024;

    #pragma unroll
    for (int i = 0; i < 4; ++i) dst[t + i * 256] = src[t + i * 256];

    if (blockIdx.x == 0) {
        const int total = B * KTOP * R3;   // 5242880
        if (out_size >= total + 2 * B * KTOP && t < B * KTOP) {
            out[total + t]            = (float)g_topidx[t];
            out[total + B * KTOP + t] = g_topval[t];
        }
    }
}

// ============================================================
extern "C" void kernel_launch(void* const* d_in, const int* in_sizes, int n_in,
                              void* d_out, int out_size) {
    const float* x    = (const float*)d_in[0];  // (32, 512)
    const float* keys = (const float*)d_in[1];  // (10000, 512)
    const float* vals = (const float*)d_in[2];  // (10000, 32, 32, 32)
    // d_in[3] = top_k (int scalar) -- fixed at 5 per problem shape

    float* out = (float*)d_out;

    k_qnorm<<<B, 128>>>(x);
    k_sim<<<(M + KPB - 1) / KPB, 256>>>(x, keys);   // 157 blocks
    k_topk<<<B, 256>>>();
    k_gather<<<B * KTOP * 8, 256>>>(vals, out, out_size);
}

// round 3
// speedup vs baseline: 1.2249x; 1.2243x over previous
#include <cuda_runtime.h>
#include <math.h>
#include <limits.h>

#define B     32
#define D     512
#define M     10000
#define KTOP  5
#define R3    32768
#define EPS   1e-12f

// sim kernel tiling
#define BN      40          // keys per block (250 * 40 = 10000 exactly)
#define STHR    160         // 5 warps
#define NCHUNK  4           // D split into 4 chunks of 128 floats (32 float4)
#define XROW    40          // xs row stride in float4 (32 + swizzle room)
#define KROW    33          // ks row stride in float4 (33 mod 8 == 1 -> conflict-free)

typedef unsigned long long ull;

// -------- device scratch (no allocation allowed) --------
__device__ float g_sim[B * M];
__device__ int   g_topidx[B * KTOP];
__device__ float g_topval[B * KTOP];

// -------- packed f32x2 helpers --------
__device__ __forceinline__ void fma2(ull& d, ull a, ull b) {
    asm("fma.rn.f32x2 %0, %1, %2, %0;" : "+l"(d) : "l"(a), "l"(b));
}
__device__ __forceinline__ float2 up2(ull v) {
    float2 f;
    asm("mov.b64 {%0, %1}, %2;" : "=f"(f.x), "=f"(f.y) : "l"(v));
    return f;
}

// ============================================================
// Kernel 1: similarity (normalization fused).
// grid = 250, block = 160 (5 warps). Block tile: 32 b x 40 keys.
// Warp tile: 32 b x 8 k.  Thread tile: 4 b x 2 k.
// Lane layout: kgrp = lane & 3 (2 keys each), bgrp = lane >> 2 (4 b each).
// acc packed along d via fma.rn.f32x2.
// ============================================================
__global__ void __launch_bounds__(STHR, 5) k_sim(const float* __restrict__ x,
                                                 const float* __restrict__ keys) {
    __shared__ float4 xs4[32 * XROW];       // swizzled: b*40 + d4c + (b>>2)
    __shared__ float4 ks4[BN * KROW];
    __shared__ float  s_rq[B];
    __shared__ float  s_rk[BN];

    const int tid  = threadIdx.x;
    const int lane = tid & 31;
    const int wid  = tid >> 5;              // 0..4
    const int kgrp = lane & 3;
    const int bgrp = lane >> 2;             // 0..7
    const int m0   = blockIdx.x * BN;

    const float4* __restrict__ x4    = (const float4*)x;     // [32][128]
    const float4* __restrict__ keys4 = (const float4*)keys;  // [10000][128]

    ull acc[4][2];
    #pragma unroll
    for (int i = 0; i < 4; ++i) { acc[i][0] = 0ull; acc[i][1] = 0ull; }

    float knp[8], qnp[7];
    #pragma unroll
    for (int r = 0; r < 8; ++r) knp[r] = 0.f;
    #pragma unroll
    for (int r = 0; r < 7; ++r) qnp[r] = 0.f;

    const float4* xp = xs4 + bgrp * (4 * XROW + 1);           // bgrp*161
    const float4* kp = ks4 + (wid * 8 + kgrp * 2) * KROW;

    #pragma unroll 1
    for (int ch = 0; ch < NCHUNK; ++ch) {
        __syncthreads();   // previous compute done before smem overwrite

        // ---- load key chunk: 40 keys x 32 f4; k = wid + 5r, d4c = lane ----
        #pragma unroll
        for (int r = 0; r < 8; ++r) {
            int flat = tid + STHR * r;
            int k    = flat >> 5;
            int d4c  = flat & 31;
            float4 v = keys4[(size_t)(m0 + k) * 128 + ch * 32 + d4c];
            knp[r] += v.x * v.x + v.y * v.y + v.z * v.z + v.w * v.w;
            ks4[k * KROW + d4c] = v;
        }
        // ---- load x chunk: 32 b x 32 f4 (swizzled) ----
        #pragma unroll
        for (int r = 0; r < 7; ++r) {
            int flat = tid + STHR * r;
            if (flat < 1024) {
                int b   = flat >> 5;
                int d4c = flat & 31;
                float4 v = x4[b * 128 + ch * 32 + d4c];
                qnp[r] += v.x * v.x + v.y * v.y + v.z * v.z + v.w * v.w;
                xs4[b * XROW + d4c + (b >> 2)] = v;
            }
        }
        __syncthreads();

        // ---- compute: 32 d4 steps, 16 fma2 each ----
        #pragma unroll
        for (int d4c = 0; d4c < 32; ++d4c) {
            ulonglong2 kv0 = *(const ulonglong2*)(kp + d4c);
            ulonglong2 kv1 = *(const ulonglong2*)(kp + KROW + d4c);
            #pragma unroll
            for (int i = 0; i < 4; ++i) {
                ulonglong2 xv = *(const ulonglong2*)(xp + i * XROW + d4c);
                fma2(acc[i][0], xv.x, kv0.x);
                fma2(acc[i][0], xv.y, kv0.y);
                fma2(acc[i][1], xv.x, kv1.x);
                fma2(acc[i][1], xv.y, kv1.y);
            }
        }
    }

    // ---- norms: warp-reduce (lanes hold distinct d4c pieces of same row) ----
    #pragma unroll
    for (int r = 0; r < 8; ++r) {
        float s = knp[r];
        #pragma unroll
        for (int o = 16; o > 0; o >>= 1) s += __shfl_xor_sync(0xFFFFFFFFu, s, o);
        if (lane == 0) s_rk[wid + 5 * r] = 1.0f / fmaxf(sqrtf(s), EPS);
    }
    #pragma unroll
    for (int r = 0; r < 7; ++r) {
        float s = qnp[r];
        #pragma unroll
        for (int o = 16; o > 0; o >>= 1) s += __shfl_xor_sync(0xFFFFFFFFu, s, o);
        int b = wid + 5 * r;
        if (lane == 0 && b < B) s_rq[b] = 1.0f / fmaxf(sqrtf(s), EPS);
    }
    __syncthreads();

    // ---- epilogue ----
    #pragma unroll
    for (int i = 0; i < 4; ++i) {
        int b = bgrp * 4 + i;
        #pragma unroll
        for (int j = 0; j < 2; ++j) {
            int kloc = wid * 8 + kgrp * 2 + j;
            float2 p = up2(acc[i][j]);
            g_sim[b * M + m0 + kloc] = (p.x + p.y) * s_rq[b] * s_rk[kloc];
        }
    }
}

// ============================================================
// Kernel 2: top-5 per row. 32 blocks x 256 (8 warps).
// Per-lane register top-5 (insertion), warp tournament, block merge.
// Tie-break: lower index (matches jax.lax.top_k).
// ============================================================
__global__ void __launch_bounds__(256) k_topk() {
    __shared__ float s_cv[40];
    __shared__ int   s_ci[40];

    const int b    = blockIdx.x;
    const int tid  = threadIdx.x;
    const int w    = tid >> 5;
    const int lane = tid & 31;
    const float* __restrict__ row = g_sim + b * M;
    const int base = w * 1250;      // 8 warps x 1250 = 10000

    float t0 = -INFINITY, t1 = -INFINITY, t2 = -INFINITY, t3 = -INFINITY, t4 = -INFINITY;
    int   x0 = INT_MAX, x1 = INT_MAX, x2 = INT_MAX, x3 = INT_MAX, x4 = INT_MAX;

    #pragma unroll 4
    for (int it = 0; it < 40; ++it) {
        int m = base + lane + 32 * it;
        if (m < base + 1250) {
            float v = row[m];
            if (v > t4) {
                if (v > t0)      { t4=t3;x4=x3; t3=t2;x3=x2; t2=t1;x2=x1; t1=t0;x1=x0; t0=v;x0=m; }
                else if (v > t1) { t4=t3;x4=x3; t3=t2;x3=x2; t2=t1;x2=x1; t1=v;x1=m; }
                else if (v > t2) { t4=t3;x4=x3; t3=t2;x3=x2; t2=v;x2=m; }
                else if (v > t3) { t4=t3;x4=x3; t3=v;x3=m; }
                else             { t4=v;x4=m; }
            }
        }
    }

    // warp tournament: 5 rounds of head-max + pop
    #pragma unroll
    for (int kk = 0; kk < 5; ++kk) {
        float bv = t0; int bi = x0;
        #pragma unroll
        for (int o = 16; o > 0; o >>= 1) {
            float ov = __shfl_xor_sync(0xFFFFFFFFu, bv, o);
            int   oi = __shfl_xor_sync(0xFFFFFFFFu, bi, o);
            if (ov > bv || (ov == bv && oi < bi)) { bv = ov; bi = oi; }
        }
        if (x0 == bi) { t0=t1;x0=x1; t1=t2;x1=x2; t2=t3;x2=x3; t3=t4;x3=x4; t4=-INFINITY;x4=INT_MAX; }
        if (lane == 0) { s_cv[w * 5 + kk] = bv; s_ci[w * 5 + kk] = bi; }
    }
    __syncthreads();

    // block merge: warp 0 over 40 candidates (2 per lane)
    if (w == 0) {
        float va = s_cv[lane];
        int   ia = s_ci[lane];
        float vb = (lane + 32 < 40) ? s_cv[lane + 32] : -INFINITY;
        int   ib = (lane + 32 < 40) ? s_ci[lane + 32] : INT_MAX;
        if (vb > va || (vb == va && ib < ia)) {
            float tv = va; va = vb; vb = tv;
            int   ti = ia; ia = ib; ib = ti;
        }
        #pragma unroll
        for (int kk = 0; kk < 5; ++kk) {
            float bv = va; int bi = ia;
            #pragma unroll
            for (int o = 16; o > 0; o >>= 1) {
                float ov = __shfl_xor_sync(0xFFFFFFFFu, bv, o);
                int   oi = __shfl_xor_sync(0xFFFFFFFFu, bi, o);
                if (ov > bv || (ov == bv && oi < bi)) { bv = ov; bi = oi; }
            }
            if (ia == bi) { va = vb; ia = ib; vb = -INFINITY; ib = INT_MAX; }
            if (lane == 0) { g_topval[b * KTOP + kk] = bv; g_topidx[b * KTOP + kk] = bi; }
        }
    }
}

// ============================================================
// Kernel 3: gather (MLP=8) + idx/vals tail.
// 320 blocks: pair = bid>>1, half = bid&1. 64KB per block.
// ============================================================
__global__ void __launch_bounds__(256) k_gather(const float* __restrict__ vals,
                                                float* __restrict__ out,
                                                int out_size) {
    const int pair = blockIdx.x >> 1;
    const int half = blockIdx.x & 1;
    const int t    = threadIdx.x;

    const int idx = g_topidx[pair];
    const float4* __restrict__ src = (const float4*)vals + (size_t)idx  * 8192 + half * 4096;
    float4*       __restrict__ dst = (float4*)out        + (size_t)pair * 8192 + half * 4096;

    float4 tmp[8];
    #pragma unroll
    for (int p = 0; p < 2; ++p) {
        #pragma unroll
        for (int i = 0; i < 8; ++i) tmp[i] = src[t + 256 * i + p * 2048];
        #pragma unroll
        for (int i = 0; i < 8; ++i) dst[t + 256 * i + p * 2048] = tmp[i];
    }

    if (blockIdx.x == 0) {
        const int total = B * KTOP * R3;   // 5242880
        if (out_size >= total + 2 * B * KTOP && t < B * KTOP) {
            out[total + t]            = (float)g_topidx[t];
            out[total + B * KTOP + t] = g_topval[t];
        }
    }
}

// ============================================================
extern "C" void kernel_launch(void* const* d_in, const int* in_sizes, int n_in,
                              void* d_out, int out_size) {
    const float* x    = (const float*)d_in[0];  // (32, 512)
    const float* keys = (const float*)d_in[1];  // (10000, 512)
    const float* vals = (const float*)d_in[2];  // (10000, 32, 32, 32)

    float* out = (float*)d_out;

    k_sim<<<M / BN, STHR>>>(x, keys);           // 250 blocks
    k_topk<<<B, 256>>>();
    k_gather<<<B * KTOP * 2, 256>>>(vals, out, out_size);
}

// round 4
// speedup vs baseline: 1.4271x; 1.1651x over previous
#include <cuda_runtime.h>
#include <math.h>
#include <limits.h>

#define B     32
#define D     512
#define M     10000
#define KTOP  5
#define R3    32768
#define EPS   1e-12f

// sim kernel tiling
#define BN    40            // keys per block (250 * 40 = 10000)
#define STHR  160           // 5 warps
#define NDQ   4             // D split into 4 quarters of 128 floats (32 float4)
#define XROW  40            // xs row stride in float4 (swizzled)
#define KROW  33            // ks row stride in float4

typedef unsigned long long ull;

// -------- device scratch (no allocation allowed) --------
__device__ float g_spart[NDQ][B * M];   // partial dots per d-quarter
__device__ float g_knp[NDQ][M];         // partial key norms^2
__device__ float g_rk[M];
__device__ float g_rq[B];
__device__ int   g_topidx[B * KTOP];
__device__ float g_topval[B * KTOP];

// -------- packed f32x2 helpers --------
__device__ __forceinline__ void fma2(ull& d, ull a, ull b) {
    asm("fma.rn.f32x2 %0, %1, %2, %0;" : "+l"(d) : "l"(a), "l"(b));
}
__device__ __forceinline__ float2 up2(ull v) {
    float2 f;
    asm("mov.b64 {%0, %1}, %2;" : "=f"(f.x), "=f"(f.y) : "l"(v));
    return f;
}

// ============================================================
// Kernel 1: partial similarity. grid = (250, 4), block = 160.
// Block: 40 keys x 32 b x 128 d (d-quarter blockIdx.y).
// Warp tile: 32 b x 8 k. Thread tile: 4 b x 2 k, d-packed fma2.
// ============================================================
__global__ void __launch_bounds__(STHR, 5) k_sim(const float* __restrict__ x,
                                                 const float* __restrict__ keys) {
    __shared__ float4 xs4[32 * XROW + 8];
    __shared__ float4 ks4[BN * KROW];

    const int tid  = threadIdx.x;
    const int lane = tid & 31;
    const int wid  = tid >> 5;           // 0..4
    const int kgrp = lane & 3;
    const int bgrp = lane >> 2;          // 0..7
    const int m0   = blockIdx.x * BN;
    const int dq   = blockIdx.y;
    const int doff = dq * 32;            // float4 offset into D

    const float4* __restrict__ x4    = (const float4*)x;     // [32][128]
    const float4* __restrict__ keys4 = (const float4*)keys;  // [10000][128]

    // ---- load key chunk: 40 keys x 32 f4 (k = wid + 5r, d4c = lane) ----
    float knp[8];
    #pragma unroll
    for (int r = 0; r < 8; ++r) {
        int flat = tid + STHR * r;
        int k    = flat >> 5;            // constant within (warp, r)
        int d4c  = flat & 31;
        float4 v = keys4[(size_t)(m0 + k) * 128 + doff + d4c];
        knp[r] = v.x * v.x + v.y * v.y + v.z * v.z + v.w * v.w;
        ks4[k * KROW + d4c] = v;
    }
    // ---- load x chunk: 32 b x 32 f4, swizzled ----
    #pragma unroll
    for (int r = 0; r < 7; ++r) {
        int flat = tid + STHR * r;
        if (flat < 1024) {
            int b   = flat >> 5;
            int d4c = flat & 31;
            xs4[b * XROW + d4c + (b >> 2)] = x4[b * 128 + doff + d4c];
        }
    }
    // key norm partials: warp-reduce, k = wid + 5r within this warp
    #pragma unroll
    for (int r = 0; r < 8; ++r) {
        float s = knp[r];
        #pragma unroll
        for (int o = 16; o > 0; o >>= 1) s += __shfl_xor_sync(0xFFFFFFFFu, s, o);
        if (lane == 0) g_knp[dq][m0 + wid + 5 * r] = s;
    }
    __syncthreads();

    // ---- compute: 32 d4 steps x 16 fma2 ----
    ull acc[4][2];
    #pragma unroll
    for (int i = 0; i < 4; ++i) { acc[i][0] = 0ull; acc[i][1] = 0ull; }

    const float4* xp = xs4 + bgrp * (4 * XROW + 1);           // bgrp*161
    const float4* kp = ks4 + (wid * 8 + kgrp * 2) * KROW;

    #pragma unroll
    for (int d4c = 0; d4c < 32; ++d4c) {
        ulonglong2 kv0 = *(const ulonglong2*)(kp + d4c);
        ulonglong2 kv1 = *(const ulonglong2*)(kp + KROW + d4c);
        #pragma unroll
        for (int i = 0; i < 4; ++i) {
            ulonglong2 xv = *(const ulonglong2*)(xp + i * XROW + d4c);
            fma2(acc[i][0], xv.x, kv0.x);
            fma2(acc[i][0], xv.y, kv0.y);
            fma2(acc[i][1], xv.x, kv1.x);
            fma2(acc[i][1], xv.y, kv1.y);
        }
    }

    // ---- epilogue: write partial dots ----
    #pragma unroll
    for (int i = 0; i < 4; ++i) {
        int b = bgrp * 4 + i;
        #pragma unroll
        for (int j = 0; j < 2; ++j) {
            int kloc = wid * 8 + kgrp * 2 + j;
            float2 p = up2(acc[i][j]);
            g_spart[dq][b * M + m0 + kloc] = p.x + p.y;
        }
    }
}

// ============================================================
// Kernel 2: norms. blocks 0..39: rk[m]; blocks 40..43: rq[b].
// ============================================================
__global__ void __launch_bounds__(256) k_nrm(const float* __restrict__ x) {
    const int bid = blockIdx.x;
    const int tid = threadIdx.x;
    if (bid < 40) {
        int m = bid * 256 + tid;
        if (m < M) {
            float s = g_knp[0][m] + g_knp[1][m] + g_knp[2][m] + g_knp[3][m];
            g_rk[m] = 1.0f / fmaxf(sqrtf(s), EPS);
        }
    } else {
        int b    = (bid - 40) * 8 + (tid >> 5);
        int lane = tid & 31;
        float s = 0.f;
        #pragma unroll
        for (int k = 0; k < 4; ++k) {
            float4 v = ((const float4*)x)[b * 128 + lane + 32 * k];
            s += v.x * v.x + v.y * v.y + v.z * v.z + v.w * v.w;
        }
        #pragma unroll
        for (int o = 16; o > 0; o >>= 1) s += __shfl_xor_sync(0xFFFFFFFFu, s, o);
        if (lane == 0) g_rq[b] = 1.0f / fmaxf(sqrtf(s), EPS);
    }
}

// ============================================================
// Kernel 3: top-5 per row over val = (sum of 4 partials) * rk[m].
// rq[b] > 0 is row-constant -> ranking invariant; applied to outputs.
// Tie-break: lower index (matches jax.lax.top_k).
// ============================================================
__global__ void __launch_bounds__(256) k_topk() {
    __shared__ float s_cv[40];
    __shared__ int   s_ci[40];

    const int b    = blockIdx.x;
    const int tid  = threadIdx.x;
    const int w    = tid >> 5;
    const int lane = tid & 31;
    const int base = w * 1250;           // 8 warps x 1250 = 10000
    const int roff = b * M;

    float t0 = -INFINITY, t1 = -INFINITY, t2 = -INFINITY, t3 = -INFINITY, t4 = -INFINITY;
    int   x0 = INT_MAX, x1 = INT_MAX, x2 = INT_MAX, x3 = INT_MAX, x4 = INT_MAX;

    #pragma unroll 4
    for (int it = 0; it < 40; ++it) {
        int m = base + lane + 32 * it;
        if (m < base + 1250) {
            float v = (g_spart[0][roff + m] + g_spart[1][roff + m] +
                       g_spart[2][roff + m] + g_spart[3][roff + m]) * g_rk[m];
            if (v > t4) {
                if (v > t0)      { t4=t3;x4=x3; t3=t2;x3=x2; t2=t1;x2=x1; t1=t0;x1=x0; t0=v;x0=m; }
                else if (v > t1) { t4=t3;x4=x3; t3=t2;x3=x2; t2=t1;x2=x1; t1=v;x1=m; }
                else if (v > t2) { t4=t3;x4=x3; t3=t2;x3=x2; t2=v;x2=m; }
                else if (v > t3) { t4=t3;x4=x3; t3=v;x3=m; }
                else             { t4=v;x4=m; }
            }
        }
    }

    #pragma unroll
    for (int kk = 0; kk < 5; ++kk) {
        float bv = t0; int bi = x0;
        #pragma unroll
        for (int o = 16; o > 0; o >>= 1) {
            float ov = __shfl_xor_sync(0xFFFFFFFFu, bv, o);
            int   oi = __shfl_xor_sync(0xFFFFFFFFu, bi, o);
            if (ov > bv || (ov == bv && oi < bi)) { bv = ov; bi = oi; }
        }
        if (x0 == bi) { t0=t1;x0=x1; t1=t2;x1=x2; t2=t3;x2=x3; t3=t4;x3=x4; t4=-INFINITY;x4=INT_MAX; }
        if (lane == 0) { s_cv[w * 5 + kk] = bv; s_ci[w * 5 + kk] = bi; }
    }
    __syncthreads();

    if (w == 0) {
        float rq = g_rq[b];
        float va = s_cv[lane];
        int   ia = s_ci[lane];
        float vb = (lane + 32 < 40) ? s_cv[lane + 32] : -INFINITY;
        int   ib = (lane + 32 < 40) ? s_ci[lane + 32] : INT_MAX;
        if (vb > va || (vb == va && ib < ia)) {
            float tv = va; va = vb; vb = tv;
            int   ti = ia; ia = ib; ib = ti;
        }
        #pragma unroll
        for (int kk = 0; kk < 5; ++kk) {
            float bv = va; int bi = ia;
            #pragma unroll
            for (int o = 16; o > 0; o >>= 1) {
                float ov = __shfl_xor_sync(0xFFFFFFFFu, bv, o);
                int   oi = __shfl_xor_sync(0xFFFFFFFFu, bi, o);
                if (ov > bv || (ov == bv && oi < bi)) { bv = ov; bi = oi; }
            }
            if (ia == bi) { va = vb; ia = ib; vb = -INFINITY; ib = INT_MAX; }
            if (lane == 0) { g_topval[b * KTOP + kk] = bv * rq; g_topidx[b * KTOP + kk] = bi; }
        }
    }
}

// ============================================================
// Kernel 4: gather (MLP=16) + idx/vals tail. 320 blocks x 64KB.
// ============================================================
__global__ void __launch_bounds__(256) k_gather(const float* __restrict__ vals,
                                                float* __restrict__ out,
                                                int out_size) {
    const int pair = blockIdx.x >> 1;
    const int half = blockIdx.x & 1;
    const int t    = threadIdx.x;

    const int idx = g_topidx[pair];
    const float4* __restrict__ src = (const float4*)vals + (size_t)idx  * 8192 + half * 4096;
    float4*       __restrict__ dst = (float4*)out        + (size_t)pair * 8192 + half * 4096;

    float4 tmp[16];
    #pragma unroll
    for (int i = 0; i < 16; ++i) tmp[i] = src[t + 256 * i];
    #pragma unroll
    for (int i = 0; i < 16; ++i) dst[t + 256 * i] = tmp[i];

    if (blockIdx.x == 0) {
        const int total = B * KTOP * R3;   // 5242880
        if (out_size >= total + 2 * B * KTOP && t < B * KTOP) {
            out[total + t]            = (float)g_topidx[t];
            out[total + B * KTOP + t] = g_topval[t];
        }
    }
}

// ============================================================
extern "C" void kernel_launch(void* const* d_in, const int* in_sizes, int n_in,
                              void* d_out, int out_size) {
    const float* x    = (const float*)d_in[0];  // (32, 512)
    const float* keys = (const float*)d_in[1];  // (10000, 512)
    const float* vals = (const float*)d_in[2];  // (10000, 32, 32, 32)

    float* out = (float*)d_out;

    k_sim<<<dim3(M / BN, NDQ), STHR>>>(x, keys);  // 1000 blocks
    k_nrm<<<44, 256>>>(x);
    k_topk<<<B, 256>>>();
    k_gather<<<B * KTOP * 2, 256>>>(vals, out, out_size);
}